// round 1
// baseline (speedup 1.0000x reference)
#include <cuda_runtime.h>
#include <cstdint>

// Problem constants
#define M_TOTAL 14400   // 16 * 30 * 30
#define N_TOTAL 512
#define K_TOTAL 1152
#define OHW     900     // 30*30
#define XSTRIDE_N 262144 // 256*32*32
#define OSTRIDE_N 460800 // 512*900

#define BM 128
#define BN 128
#define BK 32
#define NTHREADS 256
#define KCHUNKS (K_TOTAL / BK)   // 36

__device__ __forceinline__ uint32_t f2tf32(float f) {
    uint32_t r;
    asm("cvt.rna.tf32.f32 %0, %1;" : "=r"(r) : "f"(f));
    return r;
}

__global__ __launch_bounds__(NTHREADS, 1)
void masked_conv_tf32_kernel(const float* __restrict__ x,
                             const float* __restrict__ w,
                             const int*   __restrict__ idx,
                             float*       __restrict__ out)
{
    // +8 word padding: fragment LDS bank = (k*8 + m) % 32 -> conflict-free
    __shared__ uint32_t As[BK][BM + 8];
    __shared__ uint32_t Bs[BK][BN + 8];
    __shared__ int koff[K_TOTAL];
    __shared__ int mbase[BM];

    const int t  = threadIdx.x;
    const int bm = blockIdx.x;
    const int bn = blockIdx.y;

    // ---- Per-block decode tables (trivial cost, reused for all 36 k-chunks) ----
    for (int k = t; k < K_TOTAL; k += NTHREADS) {
        int v  = idx[k];            // 0..2303
        int c  = v / 9;
        int rs = v - c * 9;
        int r  = rs / 3;
        int s  = rs - r * 3;
        koff[k] = c * 1024 + r * 32 + s;
    }
    if (t < BM) {
        int m   = bm * BM + t;
        int mc  = (m < M_TOTAL) ? m : 0;     // clamp; garbage rows never stored
        int nb  = mc / OHW;
        int rem = mc - nb * OHW;
        int i   = rem / 30;
        int j   = rem - i * 30;
        mbase[t] = nb * XSTRIDE_N + i * 32 + j;
    }
    __syncthreads();

    const int lane   = t & 31;
    const int wid    = t >> 5;
    const int warp_m = wid & 1;    // 0..1 -> 64-row slab
    const int warp_n = wid >> 1;   // 0..3 -> 32-col slab
    const int gid    = lane >> 2;  // 0..7
    const int tig    = lane & 3;   // 0..3

    float acc[4][4][4];
    #pragma unroll
    for (int a = 0; a < 4; a++)
        #pragma unroll
        for (int b = 0; b < 4; b++)
            #pragma unroll
            for (int c = 0; c < 4; c++)
                acc[a][b][c] = 0.0f;

    const float* wbase = w + bn * BN;

    for (int kc = 0; kc < KCHUNKS; kc++) {
        // ---- A gather: 128 x 32 tile, m-fast for coalescing ----
        #pragma unroll
        for (int i = 0; i < 16; i++) {
            int lin = t + i * NTHREADS;
            int kk  = lin >> 7;
            int mm  = lin & 127;
            float v = __ldg(&x[mbase[mm] + koff[kc * BK + kk]]);
            As[kk][mm] = f2tf32(v);
        }
        // ---- B load: 32 x 128 tile, vectorized ----
        #pragma unroll
        for (int i = 0; i < 4; i++) {
            int lin = t + i * NTHREADS;
            int kk  = lin >> 5;
            int nn  = (lin & 31) << 2;
            float4 v = *reinterpret_cast<const float4*>(
                           wbase + (kc * BK + kk) * N_TOTAL + nn);
            Bs[kk][nn]     = f2tf32(v.x);
            Bs[kk][nn + 1] = f2tf32(v.y);
            Bs[kk][nn + 2] = f2tf32(v.z);
            Bs[kk][nn + 3] = f2tf32(v.w);
        }
        __syncthreads();

        #pragma unroll
        for (int ks = 0; ks < 4; ks++) {
            const int k0 = ks * 8 + tig;
            uint32_t afrag[4][4];
            uint32_t bfrag[4][2];
            #pragma unroll
            for (int mt = 0; mt < 4; mt++) {
                int m0 = warp_m * 64 + mt * 16 + gid;
                afrag[mt][0] = As[k0][m0];
                afrag[mt][1] = As[k0][m0 + 8];
                afrag[mt][2] = As[k0 + 4][m0];
                afrag[mt][3] = As[k0 + 4][m0 + 8];
            }
            #pragma unroll
            for (int nt = 0; nt < 4; nt++) {
                int n0 = warp_n * 32 + nt * 8 + gid;
                bfrag[nt][0] = Bs[k0][n0];
                bfrag[nt][1] = Bs[k0 + 4][n0];
            }
            #pragma unroll
            for (int mt = 0; mt < 4; mt++)
                #pragma unroll
                for (int nt = 0; nt < 4; nt++) {
                    asm volatile(
                        "mma.sync.aligned.m16n8k8.row.col.f32.tf32.tf32.f32 "
                        "{%0,%1,%2,%3}, {%4,%5,%6,%7}, {%8,%9}, {%0,%1,%2,%3};\n"
                        : "+f"(acc[mt][nt][0]), "+f"(acc[mt][nt][1]),
                          "+f"(acc[mt][nt][2]), "+f"(acc[mt][nt][3])
                        : "r"(afrag[mt][0]), "r"(afrag[mt][1]),
                          "r"(afrag[mt][2]), "r"(afrag[mt][3]),
                          "r"(bfrag[nt][0]), "r"(bfrag[nt][1]));
                }
        }
        __syncthreads();
    }

    // ---- Epilogue: out[nb, oc, p] = acc ; p = m % 900, nb = m / 900 ----
    #pragma unroll
    for (int mt = 0; mt < 4; mt++) {
        int m0 = bm * BM + warp_m * 64 + mt * 16 + gid;
        int m1 = m0 + 8;
        int nb0 = m0 / OHW, p0 = m0 - nb0 * OHW;
        int nb1 = m1 / OHW, p1 = m1 - nb1 * OHW;
        int base0 = nb0 * OSTRIDE_N + p0;
        int base1 = nb1 * OSTRIDE_N + p1;
        #pragma unroll
        for (int nt = 0; nt < 4; nt++) {
            int oc = bn * BN + warp_n * 32 + nt * 8 + tig * 2;
            if (m0 < M_TOTAL) {
                out[base0 + oc * OHW]       = acc[mt][nt][0];
                out[base0 + (oc + 1) * OHW] = acc[mt][nt][1];
            }
            if (m1 < M_TOTAL) {
                out[base1 + oc * OHW]       = acc[mt][nt][2];
                out[base1 + (oc + 1) * OHW] = acc[mt][nt][3];
            }
        }
    }
}

extern "C" void kernel_launch(void* const* d_in, const int* in_sizes, int n_in,
                              void* d_out, int out_size) {
    const float* x   = (const float*)d_in[0];   // (16,256,32,32) fp32
    const float* w   = (const float*)d_in[1];   // (1152,512) fp32
    const int*   idx = (const int*)d_in[2];     // (1152,) int32 sorted
    float*       out = (float*)d_out;           // (16,512,30,30) fp32

    dim3 grid((M_TOTAL + BM - 1) / BM, N_TOTAL / BN);  // (113, 4)
    masked_conv_tf32_kernel<<<grid, NTHREADS>>>(x, w, idx, out);
}

// round 3
// speedup vs baseline: 1.8888x; 1.8888x over previous
#include <cuda_runtime.h>
#include <cstdint>

// ---------------- problem constants ----------------
#define M_TOTAL   14400      // 16 * 30 * 30
#define N_TOTAL   512
#define K_TOTAL   1152
#define OHW       900        // 30*30
#define XSTRIDE_N 262144     // 256*32*32
#define OSTRIDE_N 460800     // 512*900
#define X_ELEMS   (16*256*32*32)

#define BM 128
#define BN 128
#define BK 32
#define NCHUNK 36            // K_TOTAL / BK
#define STAGES 4
#define NTHREADS 256
#define LDA 136              // padded row length in words (conflict-free frag LDS)

#define ASTG_BYTES (BK * LDA * 4)       // 17408 (A tile, one stage)
#define STG_BYTES  (2 * ASTG_BYTES)     // 34816 (A + B per stage)
#define SM_KOFF    (STAGES * STG_BYTES) // 139264
#define SM_TOTAL   (SM_KOFF + K_TOTAL * 4)  // 143872 bytes

// tf32-converted copies (prep kernels fill these once per launch)
__device__ float g_xc[X_ELEMS];
__device__ float g_wc[K_TOTAL * N_TOTAL];

// ---------------- helpers ----------------
__device__ __forceinline__ uint32_t smem_u32(const void* p) {
    uint32_t a;
    asm("{ .reg .u64 t; cvta.to.shared.u64 t, %1; cvt.u32.u64 %0, t; }"
        : "=r"(a) : "l"(p));
    return a;
}
__device__ __forceinline__ float f2tf32(float f) {
    uint32_t r;
    asm("cvt.rna.tf32.f32 %0, %1;" : "=r"(r) : "f"(f));
    return __uint_as_float(r);
}
__device__ __forceinline__ void cp4(uint32_t dst, const float* src) {
    asm volatile("cp.async.ca.shared.global [%0], [%1], 4;"
                 :: "r"(dst), "l"(src) : "memory");
}
__device__ __forceinline__ void cp16(uint32_t dst, const float* src) {
    asm volatile("cp.async.cg.shared.global [%0], [%1], 16;"
                 :: "r"(dst), "l"(src) : "memory");
}

// ---------------- prep: rna-convert x and w to tf32 ----------------
__global__ void conv_x_kernel(const float* __restrict__ x) {
    int i = blockIdx.x * 256 + threadIdx.x;          // float4 index
    float4 v = reinterpret_cast<const float4*>(x)[i];
    v.x = f2tf32(v.x); v.y = f2tf32(v.y); v.z = f2tf32(v.z); v.w = f2tf32(v.w);
    reinterpret_cast<float4*>(g_xc)[i] = v;
}
__global__ void conv_w_kernel(const float* __restrict__ w) {
    int i = blockIdx.x * 256 + threadIdx.x;
    float4 v = reinterpret_cast<const float4*>(w)[i];
    v.x = f2tf32(v.x); v.y = f2tf32(v.y); v.z = f2tf32(v.z); v.w = f2tf32(v.w);
    reinterpret_cast<float4*>(g_wc)[i] = v;
}

// ---------------- main fused gather-GEMM (4-stage cp.async pipeline) ----------------
__global__ __launch_bounds__(NTHREADS)
void masked_conv_pipe(const int* __restrict__ idx,
                      float*     __restrict__ out)
{
    extern __shared__ char smem[];
    const uint32_t sb = smem_u32(smem);
    const int t  = threadIdx.x;
    const int bm = blockIdx.x;
    const int bn = blockIdx.y;

    int* koff = (int*)(smem + SM_KOFF);
    for (int k = t; k < K_TOTAL; k += NTHREADS) {
        int v  = idx[k];
        int c  = v / 9;
        int rs = v - c * 9;
        koff[k] = c * 1024 + (rs / 3) * 32 + (rs % 3);
    }

    // A gather: thread owns m-row (t&127), covers kk = (t>>7) + 2i
    const int row_m = t & 127;
    const int kk0   = t >> 7;
    {
        int m_glob = bm * BM + row_m;
        int mc  = (m_glob < M_TOTAL) ? m_glob : 0;
        int nb  = mc / OHW;
        int rem = mc - nb * OHW;
        // xm kept in register below
        (void)rem;
    }
    int m_glob = bm * BM + row_m;
    int mc  = (m_glob < M_TOTAL) ? m_glob : 0;
    int nbx = mc / OHW;
    int remx = mc - nbx * OHW;
    const float* xm = g_xc + (nbx * XSTRIDE_N + (remx / 30) * 32 + (remx % 30));

    // B load: thread owns nn = (t&31)*4, covers kk = (t>>5) + 8i
    const int b_kk0 = t >> 5;
    const int b_nn  = (t & 31) << 2;
    const float* wsrc = g_wc + bn * BN + b_nn;

    __syncthreads();   // koff visible

    // ---- stage loader ----
    auto load_stage = [&](int chunk, int stg) {
        const uint32_t a_base = sb + stg * STG_BYTES;
        const uint32_t b_base = a_base + ASTG_BYTES;
        const int* kp = koff + chunk * BK;
        #pragma unroll
        for (int i = 0; i < 16; i++) {
            int kk = kk0 + 2 * i;
            cp4(a_base + (uint32_t)(kk * LDA + row_m) * 4, xm + kp[kk]);
        }
        const float* ws = wsrc + (size_t)chunk * BK * N_TOTAL;
        #pragma unroll
        for (int i = 0; i < 4; i++) {
            int kk = b_kk0 + 8 * i;
            cp16(b_base + (uint32_t)(kk * LDA + b_nn) * 4, ws + (size_t)kk * N_TOTAL);
        }
    };

    // ---- warp/fragment geometry ----
    const int lane   = t & 31;
    const int wid    = t >> 5;
    const int warp_m = wid & 1;    // 2 x 64-row slabs
    const int warp_n = wid >> 1;   // 4 x 32-col slabs
    const int gid    = lane >> 2;
    const int tig    = lane & 3;

    float acc[4][4][4];
    #pragma unroll
    for (int a = 0; a < 4; a++)
        #pragma unroll
        for (int b = 0; b < 4; b++)
            #pragma unroll
            for (int c = 0; c < 4; c++)
                acc[a][b][c] = 0.0f;

    // ---- prologue: fill stages 0..2 ----
    #pragma unroll
    for (int s = 0; s < STAGES - 1; s++) {
        load_stage(s, s);
        asm volatile("cp.async.commit_group;" ::: "memory");
    }

    // ---- main loop ----
    #pragma unroll 1
    for (int c = 0; c < NCHUNK; c++) {
        const int stg = c & (STAGES - 1);

        int pc = c + STAGES - 1;
        if (pc < NCHUNK) load_stage(pc, pc & (STAGES - 1));
        asm volatile("cp.async.commit_group;" ::: "memory");
        asm volatile("cp.async.wait_group %0;" :: "n"(STAGES - 1) : "memory");
        __syncthreads();

        const float* As = (const float*)(smem + stg * STG_BYTES);
        const float* Bs = As + ASTG_BYTES / 4;

        #pragma unroll
        for (int ks = 0; ks < 4; ks++) {
            const int k0 = ks * 8 + tig;
            uint32_t afrag[4][4];
            uint32_t bfrag[4][2];
            #pragma unroll
            for (int mt = 0; mt < 4; mt++) {
                int m0 = warp_m * 64 + mt * 16 + gid;
                afrag[mt][0] = __float_as_uint(As[k0 * LDA + m0]);
                afrag[mt][1] = __float_as_uint(As[k0 * LDA + m0 + 8]);
                afrag[mt][2] = __float_as_uint(As[(k0 + 4) * LDA + m0]);
                afrag[mt][3] = __float_as_uint(As[(k0 + 4) * LDA + m0 + 8]);
            }
            #pragma unroll
            for (int nt = 0; nt < 4; nt++) {
                int n0 = warp_n * 32 + nt * 8 + gid;
                bfrag[nt][0] = __float_as_uint(Bs[k0 * LDA + n0]);
                bfrag[nt][1] = __float_as_uint(Bs[(k0 + 4) * LDA + n0]);
            }
            #pragma unroll
            for (int mt = 0; mt < 4; mt++)
                #pragma unroll
                for (int nt = 0; nt < 4; nt++) {
                    asm volatile(
                        "mma.sync.aligned.m16n8k8.row.col.f32.tf32.tf32.f32 "
                        "{%0,%1,%2,%3}, {%4,%5,%6,%7}, {%8,%9}, {%0,%1,%2,%3};\n"
                        : "+f"(acc[mt][nt][0]), "+f"(acc[mt][nt][1]),
                          "+f"(acc[mt][nt][2]), "+f"(acc[mt][nt][3])
                        : "r"(afrag[mt][0]), "r"(afrag[mt][1]),
                          "r"(afrag[mt][2]), "r"(afrag[mt][3]),
                          "r"(bfrag[nt][0]), "r"(bfrag[nt][1]));
                }
        }
        __syncthreads();
    }

    // ---- epilogue ----
    #pragma unroll
    for (int mt = 0; mt < 4; mt++) {
        int m0 = bm * BM + warp_m * 64 + mt * 16 + gid;
        int m1 = m0 + 8;
        int nb0 = m0 / OHW, p0 = m0 - nb0 * OHW;
        int nb1 = m1 / OHW, p1 = m1 - nb1 * OHW;
        int base0 = nb0 * OSTRIDE_N + p0;
        int base1 = nb1 * OSTRIDE_N + p1;
        #pragma unroll
        for (int nt = 0; nt < 4; nt++) {
            int oc = bn * BN + warp_n * 32 + nt * 8 + tig * 2;
            if (m0 < M_TOTAL) {
                out[base0 + oc * OHW]       = acc[mt][nt][0];
                out[base0 + (oc + 1) * OHW] = acc[mt][nt][1];
            }
            if (m1 < M_TOTAL) {
                out[base1 + oc * OHW]       = acc[mt][nt][2];
                out[base1 + (oc + 1) * OHW] = acc[mt][nt][3];
            }
        }
    }
}

// ---------------- launch ----------------
extern "C" void kernel_launch(void* const* d_in, const int* in_sizes, int n_in,
                              void* d_out, int out_size) {
    const float* x   = (const float*)d_in[0];   // (16,256,32,32) fp32
    const float* w   = (const float*)d_in[1];   // (1152,512) fp32
    const int*   idx = (const int*)d_in[2];     // (1152,) int32 sorted
    float*       out = (float*)d_out;           // (16,512,30,30) fp32

    conv_x_kernel<<<X_ELEMS / 4 / 256, 256>>>(x);                 // 4096 blocks
    conv_w_kernel<<<K_TOTAL * N_TOTAL / 4 / 256, 256>>>(w);       // 576 blocks

    cudaFuncSetAttribute(masked_conv_pipe,
                         cudaFuncAttributeMaxDynamicSharedMemorySize, SM_TOTAL);
    dim3 grid((M_TOTAL + BM - 1) / BM, N_TOTAL / BN);  // (113, 4)
    masked_conv_pipe<<<grid, NTHREADS, SM_TOTAL>>>(idx, out);
}

// round 5
// speedup vs baseline: 2.5532x; 1.3517x over previous
#include <cuda_runtime.h>
#include <cstdint>

// ---------------- problem constants ----------------
#define M_TOTAL   14400      // 16 * 30 * 30
#define N_TOTAL   512
#define K_TOTAL   1152
#define OHW       900        // 30*30
#define XSTRIDE_N 262144     // 256*32*32
#define OSTRIDE_N 460800     // 512*900

#define BM 128
#define BN 128
#define BK 32
#define NCHUNK   36          // K_TOTAL / BK
#define MTILES   113         // ceil(14400/128)
#define NTHREADS 256
#define STAGES   3

// fragment-ordered staging sizes
#define A_TILE_W 4096        // words per (chunk, bm) A tile  (16 KB)
#define B_TILE_W 4096        // words per (chunk, bn) B tile  (16 KB)
#define STAGE_A_BYTES 16384
#define STAGE_B_BYTES 16384
#define STG_BYTES     32768
#define SM_TOTAL      (STAGES * STG_BYTES)    // 98304 B -> 2 CTAs/SM

// fragment-ordered scratch (filled once per launch by prep kernels)
__device__ float g_af[NCHUNK * MTILES * A_TILE_W];   // ~63.6 MB
__device__ float g_bf[NCHUNK * 4 * B_TILE_W];        // ~2.36 MB

// ---------------- helpers ----------------
__device__ __forceinline__ uint32_t smem_u32(const void* p) {
    uint32_t a;
    asm("{ .reg .u64 t; cvta.to.shared.u64 t, %1; cvt.u32.u64 %0, t; }"
        : "=r"(a) : "l"(p));
    return a;
}
__device__ __forceinline__ float f2tf32(float f) {
    uint32_t r;
    asm("cvt.rna.tf32.f32 %0, %1;" : "=r"(r) : "f"(f));
    return __uint_as_float(r);
}
__device__ __forceinline__ void cp16(uint32_t dst, const void* src) {
    asm volatile("cp.async.cg.shared.global [%0], [%1], 16;"
                 :: "r"(dst), "l"(src) : "memory");
}
__device__ __forceinline__ int dec_koff(int v) {
    int c  = v / 9;
    int rs = v - c * 9;
    return c * 1024 + (rs / 3) * 32 + (rs % 3);
}
__device__ __forceinline__ int mbase_of(int m) {
    int nb  = m / OHW;
    int rem = m - nb * OHW;
    return nb * XSTRIDE_N + (rem / 30) * 32 + (rem % 30);
}

// ---------------- prep A: gathered im2col in fragment order ----------------
// float4 f indexes [c][bmt][ks][slab][mt][lane]; the 4 words are one thread's
// afrag: (k0,m0),(k0,m0+8),(k0+4,m0),(k0+4,m0+8), k0=8ks+tig, m0=slab*64+mt*16+gid
__global__ void prep_a_kernel(const float* __restrict__ x,
                              const int*   __restrict__ idx) {
    int f = blockIdx.x * 256 + threadIdx.x;          // 0 .. 4,165,631
    int lane = f & 31;
    int mt   = (f >> 5) & 3;
    int slab = (f >> 7) & 1;
    int ks   = (f >> 8) & 3;
    int t2   = f >> 10;
    int bmt  = t2 % MTILES;
    int c    = t2 / MTILES;
    int gid  = lane >> 2, tig = lane & 3;

    int m0 = bmt * BM + slab * 64 + mt * 16 + gid;
    int m1 = m0 + 8;
    if (m0 >= M_TOTAL) m0 = 0;
    if (m1 >= M_TOTAL) m1 = 0;
    int k0 = c * BK + ks * 8 + tig;

    int ko0 = dec_koff(idx[k0]);
    int ko1 = dec_koff(idx[k0 + 4]);
    int mb0 = mbase_of(m0);
    int mb1 = mbase_of(m1);

    float4 o;
    o.x = f2tf32(__ldg(x + mb0 + ko0));
    o.y = f2tf32(__ldg(x + mb1 + ko0));
    o.z = f2tf32(__ldg(x + mb0 + ko1));
    o.w = f2tf32(__ldg(x + mb1 + ko1));
    reinterpret_cast<float4*>(g_af)[f] = o;
}

// ---------------- prep B: weights in fragment order ----------------
// float2 f indexes [c][nblk][ks][warp_n][nt][lane]; words (k0,n0),(k0+4,n0)
// per (c,nblk): 4*4*4*32 = 2048 float2 = 16 KB
__global__ void prep_b_kernel(const float* __restrict__ w) {
    int f = blockIdx.x * 256 + threadIdx.x;          // 0 .. 294,911
    int lane = f & 31;
    int nt   = (f >> 5) & 3;
    int wn   = (f >> 7) & 3;
    int ks   = (f >> 9) & 3;
    int nblk = (f >> 11) & 3;
    int c    = f >> 13;
    int gid  = lane >> 2, tig = lane & 3;

    int n = nblk * BN + wn * 32 + nt * 8 + gid;
    int k = c * BK + ks * 8 + tig;
    float2 o;
    o.x = f2tf32(__ldg(w + k * N_TOTAL + n));
    o.y = f2tf32(__ldg(w + (k + 4) * N_TOTAL + n));
    reinterpret_cast<float2*>(g_bf)[f] = o;
}

// ---------------- main streaming GEMM ----------------
__global__ __launch_bounds__(NTHREADS, 2)
void masked_conv_main(float* __restrict__ out)
{
    extern __shared__ char smem[];
    const uint32_t sb = smem_u32(smem);
    const int t  = threadIdx.x;
    const int bn = blockIdx.x;   // fast dim -> bn-blocks of same bm co-scheduled
    const int bm = blockIdx.y;

    const int lane   = t & 31;
    const int wid    = t >> 5;
    const int warp_m = wid & 1;
    const int warp_n = wid >> 1;
    const int gid    = lane >> 2;
    const int tig    = lane & 3;

    float acc[4][4][4];
    #pragma unroll
    for (int a = 0; a < 4; a++)
        #pragma unroll
        for (int b = 0; b < 4; b++)
            #pragma unroll
            for (int c = 0; c < 4; c++)
                acc[a][b][c] = 0.0f;

    auto load_stage = [&](int chunk, int stg) {
        const float4* asrc = reinterpret_cast<const float4*>(g_af)
                             + (size_t)(chunk * MTILES + bm) * (A_TILE_W / 4) + t;
        uint32_t ad = sb + stg * STG_BYTES + t * 16;
        #pragma unroll
        for (int j = 0; j < 4; j++)
            cp16(ad + j * 4096, asrc + j * 256);
        const float4* bsrc = reinterpret_cast<const float4*>(g_bf)
                             + (size_t)(chunk * 4 + bn) * (B_TILE_W / 4) + t;
        uint32_t bd = sb + stg * STG_BYTES + STAGE_A_BYTES + t * 16;
        #pragma unroll
        for (int j = 0; j < 4; j++)
            cp16(bd + j * 4096, bsrc + j * 256);
    };

    #pragma unroll
    for (int s = 0; s < STAGES - 1; s++) {
        load_stage(s, s);
        asm volatile("cp.async.commit_group;" ::: "memory");
    }

    int stg = 0;
    #pragma unroll 1
    for (int c = 0; c < NCHUNK; c++) {
        int pc = c + STAGES - 1;
        if (pc < NCHUNK) {
            int pstg = pc - STAGES * (pc / STAGES);
            load_stage(pc, pstg);
        }
        asm volatile("cp.async.commit_group;" ::: "memory");
        asm volatile("cp.async.wait_group %0;" :: "n"(STAGES - 1) : "memory");
        __syncthreads();

        const uint32_t As = sb + stg * STG_BYTES;
        const uint32_t Bs = As + STAGE_A_BYTES;

        #pragma unroll
        for (int ks = 0; ks < 4; ks++) {
            uint32_t afrag[4][4];
            uint32_t bfrag[4][2];
            #pragma unroll
            for (int mt = 0; mt < 4; mt++) {
                uint32_t addr = As + ((((ks * 2 + warp_m) * 4 + mt) * 32 + lane) << 4);
                asm volatile("ld.shared.v4.b32 {%0,%1,%2,%3}, [%4];"
                             : "=r"(afrag[mt][0]), "=r"(afrag[mt][1]),
                               "=r"(afrag[mt][2]), "=r"(afrag[mt][3])
                             : "r"(addr));
            }
            #pragma unroll
            for (int nt = 0; nt < 4; nt++) {
                uint32_t addr = Bs + ((((ks * 4 + warp_n) * 4 + nt) * 32 + lane) << 3);
                asm volatile("ld.shared.v2.b32 {%0,%1}, [%2];"
                             : "=r"(bfrag[nt][0]), "=r"(bfrag[nt][1])
                             : "r"(addr));
            }
            #pragma unroll
            for (int mt = 0; mt < 4; mt++)
                #pragma unroll
                for (int nt = 0; nt < 4; nt++) {
                    asm volatile(
                        "mma.sync.aligned.m16n8k8.row.col.f32.tf32.tf32.f32 "
                        "{%0,%1,%2,%3}, {%4,%5,%6,%7}, {%8,%9}, {%0,%1,%2,%3};\n"
                        : "+f"(acc[mt][nt][0]), "+f"(acc[mt][nt][1]),
                          "+f"(acc[mt][nt][2]), "+f"(acc[mt][nt][3])
                        : "r"(afrag[mt][0]), "r"(afrag[mt][1]),
                          "r"(afrag[mt][2]), "r"(afrag[mt][3]),
                          "r"(bfrag[nt][0]), "r"(bfrag[nt][1]));
                }
        }
        __syncthreads();

        stg = (stg == STAGES - 1) ? 0 : stg + 1;
    }

    // ---- epilogue ----
    #pragma unroll
    for (int mt = 0; mt < 4; mt++) {
        int m0 = bm * BM + warp_m * 64 + mt * 16 + gid;
        int m1 = m0 + 8;
        int nb0 = m0 / OHW, p0 = m0 - nb0 * OHW;
        int nb1 = m1 / OHW, p1 = m1 - nb1 * OHW;
        int base0 = nb0 * OSTRIDE_N + p0;
        int base1 = nb1 * OSTRIDE_N + p1;
        #pragma unroll
        for (int nt = 0; nt < 4; nt++) {
            int oc = bn * BN + warp_n * 32 + nt * 8 + tig * 2;
            if (m0 < M_TOTAL) {
                out[base0 + oc * OHW]       = acc[mt][nt][0];
                out[base0 + (oc + 1) * OHW] = acc[mt][nt][1];
            }
            if (m1 < M_TOTAL) {
                out[base1 + oc * OHW]       = acc[mt][nt][2];
                out[base1 + (oc + 1) * OHW] = acc[mt][nt][3];
            }
        }
    }
}

// ---------------- launch ----------------
extern "C" void kernel_launch(void* const* d_in, const int* in_sizes, int n_in,
                              void* d_out, int out_size) {
    const float* x   = (const float*)d_in[0];   // (16,256,32,32) fp32
    const float* w   = (const float*)d_in[1];   // (1152,512) fp32
    const int*   idx = (const int*)d_in[2];     // (1152,) int32 sorted
    float*       out = (float*)d_out;           // (16,512,30,30) fp32

    prep_a_kernel<<<16272, 256>>>(x, idx);      // 4,165,632 float4s
    prep_b_kernel<<<1152, 256>>>(w);            // 294,912 float2s

    cudaFuncSetAttribute(masked_conv_main,
                         cudaFuncAttributeMaxDynamicSharedMemorySize, SM_TOTAL);
    dim3 grid(N_TOTAL / BN, MTILES);            // (4, 113): bn fast for A L2 reuse
    masked_conv_main<<<grid, NTHREADS, SM_TOTAL>>>(out);
}

// round 7
// speedup vs baseline: 5.3032x; 2.0771x over previous
#include <cuda_runtime.h>
#include <cuda_fp16.h>
#include <cstdint>

// ---------------- problem constants ----------------
#define M_TOTAL   14400      // 16 * 30 * 30
#define N_TOTAL   512
#define K_TOTAL   1152
#define OHW       900        // 30*30
#define XSTRIDE_N 262144     // 256*32*32
#define OSTRIDE_N 460800     // 512*900

#define BM 128
#define BN 128
#define BK 32
#define NCHUNK   36          // K_TOTAL / BK
#define MTILES   113         // ceil(14400/128)
#define NTHREADS 256
#define STAGES   4

// fp16 fragment-ordered tiles: A (chunk,bm) = 128x32 half = 8 KB = 512 uint4
//                              B (chunk,bn) = 32x128 half = 8 KB = 512 uint4
#define STAGE_A_BYTES 8192
#define STG_BYTES     16384
#define SM_TOTAL      (STAGES * STG_BYTES)    // 65536 B -> 2 CTAs/SM

__device__ uint4 g_ah[NCHUNK * MTILES * 512];   // ~33.3 MB
__device__ uint4 g_bh[NCHUNK * 4 * 512];        // ~1.2 MB

// ---------------- helpers ----------------
__device__ __forceinline__ uint32_t smem_u32(const void* p) {
    uint32_t a;
    asm("{ .reg .u64 t; cvta.to.shared.u64 t, %1; cvt.u32.u64 %0, t; }"
        : "=r"(a) : "l"(p));
    return a;
}
__device__ __forceinline__ void cp16(uint32_t dst, const void* src) {
    asm volatile("cp.async.cg.shared.global [%0], [%1], 16;"
                 :: "r"(dst), "l"(src) : "memory");
}
// pack two floats into f16x2 word: lo = a, hi = b
// PTX: cvt.rn.f16x2.f32 d, x, y  ->  d.hi = f16(x), d.lo = f16(y)
__device__ __forceinline__ uint32_t h2(float a, float b) {
    uint32_t r;
    asm("cvt.rn.f16x2.f32 %0, %1, %2;" : "=r"(r) : "f"(b), "f"(a));
    return r;
}

// ---------------- prep A: gathered im2col, fp16, fragment order ----------------
// block = one (chunk c, mtile bmt). Tile = 512 fragments (uint4), fragment
// fi = (((ks*2+slab)*4+mt)*32+lane); words are a0..a3 of m16n8k16:
//   a0={A[m0][k0],A[m0][k0+1]} a1={A[m1][..]} a2={A[m0][k0+8],[k0+9]} a3={A[m1][..]}
//   m0 = slab*64+mt*16+gid, m1 = m0+8, k0 = ks*16 + 2*tig (within chunk)
__global__ void prep_a_kernel(const float* __restrict__ x,
                              const int*   __restrict__ idx) {
    __shared__ int skoff[BK];
    __shared__ int smb[BM];
    const int c   = blockIdx.x;
    const int bmt = blockIdx.y;
    const int t   = threadIdx.x;

    if (t < BK) {
        int v  = idx[c * BK + t];
        int ch = v / 9;
        int rs = v - ch * 9;
        skoff[t] = ch * 1024 + (rs / 3) * 32 + (rs % 3);
    }
    if (t < BM) {
        int m = bmt * BM + t;
        if (m >= M_TOTAL) m = 0;
        int nb  = m / OHW;
        int rem = m - nb * OHW;
        smb[t] = nb * XSTRIDE_N + (rem / 30) * 32 + (rem % 30);
    }
    __syncthreads();

    uint4* dst = g_ah + (size_t)(c * MTILES + bmt) * 512;
    #pragma unroll
    for (int fi = t; fi < 512; fi += NTHREADS) {
        int lane = fi & 31;
        int mt   = (fi >> 5) & 3;
        int slab = (fi >> 7) & 1;
        int ks   = (fi >> 8) & 1;
        int gid  = lane >> 2, tig = lane & 3;

        int mrow = slab * 64 + mt * 16 + gid;
        int mb0  = smb[mrow];
        int mb1  = smb[mrow + 8];
        int kb   = ks * 16 + tig * 2;
        int ko0 = skoff[kb],     ko1 = skoff[kb + 1];
        int ko8 = skoff[kb + 8], ko9 = skoff[kb + 9];

        uint4 o;
        o.x = h2(__ldg(x + mb0 + ko0), __ldg(x + mb0 + ko1));
        o.y = h2(__ldg(x + mb1 + ko0), __ldg(x + mb1 + ko1));
        o.z = h2(__ldg(x + mb0 + ko8), __ldg(x + mb0 + ko9));
        o.w = h2(__ldg(x + mb1 + ko8), __ldg(x + mb1 + ko9));
        dst[fi] = o;
    }
}

// ---------------- prep B: weights, fp16, fragment order ----------------
// block = one (chunk c, nblk). 1024 fragments (uint2), fragment
// fi = (((ks*4+wn)*4+nt)*32+lane); words b0,b1 of m16n8k16 (col-major B):
//   b0={B[k0][n],B[k0+1][n]} b1={B[k0+8][n],B[k0+9][n]}
//   n = wn*32+nt*8+gid, k0 = ks*16 + 2*tig (within chunk)
__global__ void prep_b_kernel(const float* __restrict__ w) {
    const int c    = blockIdx.x;
    const int nblk = blockIdx.y;
    const int t    = threadIdx.x;

    uint2* dst = reinterpret_cast<uint2*>(g_bh + (size_t)(c * 4 + nblk) * 512);
    #pragma unroll
    for (int fi = t; fi < 1024; fi += NTHREADS) {
        int lane = fi & 31;
        int nt   = (fi >> 5) & 3;
        int wn   = (fi >> 7) & 3;
        int ks   = (fi >> 9) & 1;
        int gid  = lane >> 2, tig = lane & 3;

        int n = nblk * BN + wn * 32 + nt * 8 + gid;
        int k = c * BK + ks * 16 + tig * 2;
        const float* wp = w + (size_t)k * N_TOTAL + n;
        uint2 o;
        o.x = h2(wp[0],            wp[N_TOTAL]);
        o.y = h2(wp[8 * N_TOTAL],  wp[9 * N_TOTAL]);
        dst[fi] = o;
    }
}

// ---------------- main streaming fp16 GEMM ----------------
__global__ __launch_bounds__(NTHREADS, 2)
void masked_conv_main(float* __restrict__ out)
{
    extern __shared__ char smem[];
    const uint32_t sb = smem_u32(smem);
    const int t  = threadIdx.x;
    const int bn = blockIdx.x;   // fast dim -> A tile reused in L2 across bn
    const int bm = blockIdx.y;

    const int lane   = t & 31;
    const int wid    = t >> 5;
    const int warp_m = wid & 1;
    const int warp_n = wid >> 1;
    const int gid    = lane >> 2;
    const int tig    = lane & 3;

    float acc[4][4][4];
    #pragma unroll
    for (int a = 0; a < 4; a++)
        #pragma unroll
        for (int b = 0; b < 4; b++)
            #pragma unroll
            for (int c = 0; c < 4; c++)
                acc[a][b][c] = 0.0f;

    auto load_stage = [&](int chunk, int stg) {
        const uint4* asrc = g_ah + (size_t)(chunk * MTILES + bm) * 512 + t;
        uint32_t ad = sb + stg * STG_BYTES + t * 16;
        cp16(ad, asrc);
        cp16(ad + 4096, asrc + 256);
        const uint4* bsrc = g_bh + (size_t)(chunk * 4 + bn) * 512 + t;
        uint32_t bd = ad + STAGE_A_BYTES;
        cp16(bd, bsrc);
        cp16(bd + 4096, bsrc + 256);
    };

    #pragma unroll
    for (int s = 0; s < STAGES - 1; s++) {
        load_stage(s, s);
        asm volatile("cp.async.commit_group;" ::: "memory");
    }

    #pragma unroll 1
    for (int c = 0; c < NCHUNK; c++) {
        const int stg = c & (STAGES - 1);
        int pc = c + STAGES - 1;
        if (pc < NCHUNK) load_stage(pc, pc & (STAGES - 1));
        asm volatile("cp.async.commit_group;" ::: "memory");
        asm volatile("cp.async.wait_group %0;" :: "n"(STAGES - 1) : "memory");
        __syncthreads();

        const uint32_t As = sb + stg * STG_BYTES;
        const uint32_t Bs = As + STAGE_A_BYTES;

        #pragma unroll
        for (int ks = 0; ks < 2; ks++) {
            uint32_t afrag[4][4];
            uint32_t bfrag[4][2];
            #pragma unroll
            for (int mt = 0; mt < 4; mt++) {
                uint32_t addr = As + ((((ks * 2 + warp_m) * 4 + mt) * 32 + lane) << 4);
                asm volatile("ld.shared.v4.b32 {%0,%1,%2,%3}, [%4];"
                             : "=r"(afrag[mt][0]), "=r"(afrag[mt][1]),
                               "=r"(afrag[mt][2]), "=r"(afrag[mt][3])
                             : "r"(addr));
            }
            #pragma unroll
            for (int nt = 0; nt < 4; nt++) {
                uint32_t addr = Bs + ((((ks * 4 + warp_n) * 4 + nt) * 32 + lane) << 3);
                asm volatile("ld.shared.v2.b32 {%0,%1}, [%2];"
                             : "=r"(bfrag[nt][0]), "=r"(bfrag[nt][1])
                             : "r"(addr));
            }
            #pragma unroll
            for (int mt = 0; mt < 4; mt++)
                #pragma unroll
                for (int nt = 0; nt < 4; nt++) {
                    asm volatile(
                        "mma.sync.aligned.m16n8k16.row.col.f32.f16.f16.f32 "
                        "{%0,%1,%2,%3}, {%4,%5,%6,%7}, {%8,%9}, {%0,%1,%2,%3};\n"
                        : "+f"(acc[mt][nt][0]), "+f"(acc[mt][nt][1]),
                          "+f"(acc[mt][nt][2]), "+f"(acc[mt][nt][3])
                        : "r"(afrag[mt][0]), "r"(afrag[mt][1]),
                          "r"(afrag[mt][2]), "r"(afrag[mt][3]),
                          "r"(bfrag[nt][0]), "r"(bfrag[nt][1]));
                }
        }
        __syncthreads();
    }

    // ---- epilogue ----
    #pragma unroll
    for (int mt = 0; mt < 4; mt++) {
        int m0 = bm * BM + warp_m * 64 + mt * 16 + gid;
        int m1 = m0 + 8;
        int nb0 = m0 / OHW, p0 = m0 - nb0 * OHW;
        int nb1 = m1 / OHW, p1 = m1 - nb1 * OHW;
        int base0 = nb0 * OSTRIDE_N + p0;
        int base1 = nb1 * OSTRIDE_N + p1;
        #pragma unroll
        for (int nt = 0; nt < 4; nt++) {
            int oc = bn * BN + warp_n * 32 + nt * 8 + tig * 2;
            if (m0 < M_TOTAL) {
                out[base0 + oc * OHW]       = acc[mt][nt][0];
                out[base0 + (oc + 1) * OHW] = acc[mt][nt][1];
            }
            if (m1 < M_TOTAL) {
                out[base1 + oc * OHW]       = acc[mt][nt][2];
                out[base1 + (oc + 1) * OHW] = acc[mt][nt][3];
            }
        }
    }
}

// ---------------- launch ----------------
extern "C" void kernel_launch(void* const* d_in, const int* in_sizes, int n_in,
                              void* d_out, int out_size) {
    const float* x   = (const float*)d_in[0];   // (16,256,32,32) fp32
    const float* w   = (const float*)d_in[1];   // (1152,512) fp32
    const int*   idx = (const int*)d_in[2];     // (1152,) int32 sorted
    float*       out = (float*)d_out;           // (16,512,30,30) fp32

    prep_a_kernel<<<dim3(NCHUNK, MTILES), NTHREADS>>>(x, idx);
    prep_b_kernel<<<dim3(NCHUNK, 4), NTHREADS>>>(w);

    cudaFuncSetAttribute(masked_conv_main,
                         cudaFuncAttributeMaxDynamicSharedMemorySize, SM_TOTAL);
    dim3 grid(N_TOTAL / BN, MTILES);            // (4, 113)
    masked_conv_main<<<grid, NTHREADS, SM_TOTAL>>>(out);
}